// round 6
// baseline (speedup 1.0000x reference)
#include <cuda_runtime.h>
#include <cstddef>

// FusionAdjacency: Af = rownorm( sigmoid(g)*scatter(s) + (1-sigmoid(g))*scatter(t) )
//
// R5: chunked fill+scatter pipeline. Kernel i fills row-chunk i (plain stores,
// lines stay L2-resident) and scatters row-chunk i-2 (atomics hit L2, each
// output line reaches DRAM once with its final value). hist is folded into
// kernel 0, finalize into kernel 1. finalize re-zeros g_rowsum for the next
// graph replay (module-load zero-init covers the first call).

#define NN 8192
#define NCHUNK 8
#define RPC (NN / NCHUNK)   // 1024 rows per chunk = 32 MB

__device__ float g_rowsum[NN];   // zero at load; finalize re-zeros each call
__device__ float g_rowinv[NN];

__global__ __launch_bounds__(256) void fused_kernel(
        const int* __restrict__ rows_s, const int* __restrict__ cols_s,
        const float* __restrict__ vals_s, int Es,
        const int* __restrict__ rows_t, const int* __restrict__ cols_t,
        const float* __restrict__ vals_t, int Et,
        const float* __restrict__ gamma, float* __restrict__ out,
        int fill_lo_row, int fill_rows,
        int scat_lo_row, int scat_rows,
        int do_hist, int do_finalize) {
    const int tid = blockIdx.x * blockDim.x + threadIdx.x;
    const int stride = gridDim.x * blockDim.x;
    const float g = gamma[0];
    const float alpha = 1.0f / (1.0f + expf(-g));
    const float beta = 1.0f - alpha;

    // ---- hist (kernel 0 only): blended row sums, L2-resident atomics ----
    if (do_hist) {
        for (int e = tid; e < Es; e += stride)
            atomicAdd(&g_rowsum[__ldg(&rows_s[e])], alpha * __ldg(&vals_s[e]));
        for (int e = tid; e < Et; e += stride)
            atomicAdd(&g_rowsum[__ldg(&rows_t[e])], beta * __ldg(&vals_t[e]));
    }

    // ---- finalize (kernel 1 only): guarded reciprocal + re-zero rowsum ----
    if (do_finalize) {
        for (int i = tid; i < NN; i += stride) {
            float s = g_rowsum[i];
            g_rowinv[i] = (s == 0.0f) ? 1.0f : (1.0f / s);
            g_rowsum[i] = 0.0f;
        }
    }

    // ---- scatter chunk [scat_lo, scat_lo+scat_rows): atomics into L2-hot
    //      lines filled two kernels ago. Issued BEFORE the fill loop so the
    //      long-latency REDs overlap the DRAM-bound stores. ----
    if (scat_rows > 0) {
        const unsigned lo = (unsigned)scat_lo_row;
        const unsigned nr = (unsigned)scat_rows;
        for (int e = tid; e < Es; e += stride) {
            int r = __ldg(&rows_s[e]);
            if ((unsigned)(r - lo) < nr) {
                float contrib = alpha * __ldg(&vals_s[e]) * g_rowinv[r];
                atomicAdd(&out[((size_t)r << 13) + __ldg(&cols_s[e])], contrib);
            }
        }
        for (int e = tid; e < Et; e += stride) {
            int r = __ldg(&rows_t[e]);
            if ((unsigned)(r - lo) < nr) {
                float contrib = beta * __ldg(&vals_t[e]) * g_rowinv[r];
                atomicAdd(&out[((size_t)r << 13) + __ldg(&cols_t[e])], contrib);
            }
        }
    }

    // ---- fill chunk [fill_lo, fill_lo+fill_rows) with zeros.
    //      Plain (evict-normal) float4 stores so the lines remain in L2 for
    //      the scatter two kernels later. ----
    if (fill_rows > 0) {
        float4* out4 = reinterpret_cast<float4*>(out + (size_t)fill_lo_row * NN);
        const int n4 = fill_rows * (NN / 4);
        const float4 z = make_float4(0.f, 0.f, 0.f, 0.f);
        for (int i = tid; i < n4; i += stride) {
            out4[i] = z;
        }
    }
}

extern "C" void kernel_launch(void* const* d_in, const int* in_sizes, int n_in,
                              void* d_out, int out_size) {
    const int*   rows_s = (const int*)d_in[0];
    const int*   cols_s = (const int*)d_in[1];
    const float* vals_s = (const float*)d_in[2];
    const int*   rows_t = (const int*)d_in[3];
    const int*   cols_t = (const int*)d_in[4];
    const float* vals_t = (const float*)d_in[5];
    const float* gamma  = (const float*)d_in[6];
    float* out = (float*)d_out;

    const int Es = in_sizes[0];
    const int Et = in_sizes[3];

    const int G = 2368;   // 16 blocks/SM x 148 SMs
    const int T = 256;

    // K0: hist + fill chunk 0
    fused_kernel<<<G, T>>>(rows_s, cols_s, vals_s, Es,
                           rows_t, cols_t, vals_t, Et, gamma, out,
                           /*fill*/ 0, RPC, /*scat*/ 0, 0,
                           /*hist*/ 1, /*fin*/ 0);

    // K1: finalize + fill chunk 1
    fused_kernel<<<G, T>>>(rows_s, cols_s, vals_s, Es,
                           rows_t, cols_t, vals_t, Et, gamma, out,
                           /*fill*/ RPC, RPC, /*scat*/ 0, 0,
                           /*hist*/ 0, /*fin*/ 1);

    // K2..K7: fill chunk c + scatter chunk c-2
    for (int c = 2; c < NCHUNK; c++) {
        fused_kernel<<<G, T>>>(rows_s, cols_s, vals_s, Es,
                               rows_t, cols_t, vals_t, Et, gamma, out,
                               /*fill*/ c * RPC, RPC,
                               /*scat*/ (c - 2) * RPC, RPC,
                               0, 0);
    }

    // K8: scatter the last two chunks (6 and 7)
    fused_kernel<<<G, T>>>(rows_s, cols_s, vals_s, Es,
                           rows_t, cols_t, vals_t, Et, gamma, out,
                           /*fill*/ 0, 0,
                           /*scat*/ (NCHUNK - 2) * RPC, 2 * RPC,
                           0, 0);
}